// round 2
// baseline (speedup 1.0000x reference)
#include <cuda_runtime.h>

#define HW 4096
#define BATCH 4

// ---------------- scratch (device globals; no allocation allowed) ----------
__device__ float g_q[2][BATCH][64][HW];      // 8 MB  (conv1x1 outputs, [d][n])
__device__ float g_k[2][BATCH][64][HW];      // 8 MB
__device__ float g_v[2][BATCH][64][HW];      // 8 MB
__device__ float g_z[2][BATCH][HW * 64];     // 8 MB  (attn output, [n][c])
__device__ float g_comb[BATCH][128][HW];     // 8 MB  (concat[xa, ha])
__device__ float g_y[BATCH][256][HW];        // 16 MB (3x3 conv output)
__device__ float g_mean[BATCH][256];
__device__ float g_rstd[BATCH][256];

// ---------------- generic conv1x1 GEMM: out[o,p] = sum_i w[o,i] in[i,p] ----
// tile: 64 o x 128 p, full K=64. Optional fused z-multiply on the input and
// residual add in the epilogue.  dynamic smem = 49152 B.
__global__ __launch_bounds__(256) void gemm1x1_kernel(
    const float* __restrict__ in,     // [B][64][HW]
    const float* __restrict__ w,      // [64][64]  (o-major)
    const float* __restrict__ bias,   // [64]
    const float* __restrict__ zsrc,   // optional: [B][HW*64], multiplied into in
    const float* __restrict__ resid,  // optional: [B][64][HW]
    float* __restrict__ out, int outBS)
{
    extern __shared__ float sm[];
    float* ws  = sm;         // [64][64]  ws[i*64+o] = w[o][i]
    float* ins = sm + 4096;  // [64][128]
    const int b   = blockIdx.y;
    const int p0  = blockIdx.x * 128;
    const int tid = threadIdx.x;
    const float* inB = in + (size_t)b * 64 * HW;

    for (int idx = tid; idx < 4096; idx += 256) {
        int i = idx >> 6, o = idx & 63;
        ws[idx] = w[o * 64 + i];
    }
    if (zsrc) {
        const float* zB = zsrc + (size_t)b * HW * 64;
        for (int idx = tid; idx < 8192; idx += 256) {
            int i = idx >> 7, pp = idx & 127;
            int p = p0 + pp;
            int hh = p >> 6, wc = p & 63;
            // faithful raw reshape: z viewed [C,H,W] <- contiguous [HW,C]
            ins[idx] = zB[(i * 64 + hh) * 64 + wc] * inB[i * HW + p];
        }
    } else {
        for (int idx = tid; idx < 8192; idx += 256) {
            int i = idx >> 7, pp = idx & 127;
            ins[idx] = inB[i * HW + p0 + pp];
        }
    }
    __syncthreads();

    const int tx = tid & 15, ty = tid >> 4;
    const int o0 = ty * 4, q0 = tx * 8;
    float acc[4][8];
#pragma unroll
    for (int a = 0; a < 4; a++)
#pragma unroll
        for (int c = 0; c < 8; c++) acc[a][c] = 0.f;

#pragma unroll 4
    for (int i = 0; i < 64; i++) {
        float4 w4 = *(const float4*)&ws[i * 64 + o0];
        float4 v0 = *(const float4*)&ins[i * 128 + q0];
        float4 v1 = *(const float4*)&ins[i * 128 + q0 + 4];
        float wr[4] = {w4.x, w4.y, w4.z, w4.w};
        float iv[8] = {v0.x, v0.y, v0.z, v0.w, v1.x, v1.y, v1.z, v1.w};
#pragma unroll
        for (int a = 0; a < 4; a++)
#pragma unroll
            for (int c = 0; c < 8; c++) acc[a][c] += wr[a] * iv[c];
    }

#pragma unroll
    for (int a = 0; a < 4; a++) {
        int o = o0 + a;
        float bb = bias[o];
#pragma unroll
        for (int c = 0; c < 8; c++) {
            float r = acc[a][c] + bb;
            int p = p0 + q0 + c;
            if (resid) r += resid[(size_t)b * 64 * HW + o * HW + p];
            out[(size_t)b * outBS + o * HW + p] = r;
        }
    }
}

// ---------------- flash attention --------------------------------------
// grid (32 q-tiles of 128, BATCH, 2 attn blocks), 256 threads.
// z[n,c] = sum_m softmax_m(q_n . k_m) * v[c,m]   (no 1/sqrt(d), faithful)
#define FLASH_SMEM_FLOATS (8192 + 4096 + 64 * 68 + 64 * 132)
__global__ __launch_bounds__(256, 2) void flash_kernel()
{
    extern __shared__ float sm[];
    float* qs  = sm;                  // [64 d][128 r]
    float* ks  = sm + 8192;           // [64 d][64 m]
    float* vsT = sm + 8192 + 4096;    // [64 m][68]  vsT[m][c]
    float* psT = vsT + 64 * 68;       // [64 m][132] psT[m][r]

    const int a = blockIdx.z, b = blockIdx.y;
    const int n0 = blockIdx.x * 128;
    const float* qb = &g_q[a][b][0][0];
    const float* kb = &g_k[a][b][0][0];
    const float* vb = &g_v[a][b][0][0];
    const int tid = threadIdx.x;
    const int tx = tid & 15, ty = tid >> 4;

    for (int idx = tid; idx < 8192; idx += 256) {
        int d = idx >> 7, r = idx & 127;
        qs[idx] = qb[d * HW + n0 + r];
    }

    float O[8][4];
    float mrun[8], lrun[8];
#pragma unroll
    for (int i = 0; i < 8; i++) {
        mrun[i] = -1e30f; lrun[i] = 0.f;
#pragma unroll
        for (int j = 0; j < 4; j++) O[i][j] = 0.f;
    }

    for (int m0 = 0; m0 < HW; m0 += 64) {
        __syncthreads();
        for (int idx = tid; idx < 4096; idx += 256) {
            int d = idx >> 6, m = idx & 63;
            ks[idx] = kb[d * HW + m0 + m];
        }
        for (int idx = tid; idx < 4096; idx += 256) {
            int c = idx >> 6, m = idx & 63;
            vsT[m * 68 + c] = vb[c * HW + m0 + m];
        }
        __syncthreads();

        // ---- S = Q . K   (8x4 per thread) ----
        float S[8][4];
#pragma unroll
        for (int i = 0; i < 8; i++)
#pragma unroll
            for (int j = 0; j < 4; j++) S[i][j] = 0.f;

#pragma unroll 4
        for (int d = 0; d < 64; d++) {
            float4 k4 = *(const float4*)&ks[d * 64 + tx * 4];
            float4 q0v = *(const float4*)&qs[d * 128 + ty * 8];
            float4 q1v = *(const float4*)&qs[d * 128 + ty * 8 + 4];
            float kv[4] = {k4.x, k4.y, k4.z, k4.w};
            float qv[8] = {q0v.x, q0v.y, q0v.z, q0v.w, q1v.x, q1v.y, q1v.z, q1v.w};
#pragma unroll
            for (int i = 0; i < 8; i++)
#pragma unroll
                for (int j = 0; j < 4; j++) S[i][j] += qv[i] * kv[j];
        }

        // ---- online softmax (rows owned by the 16 tx lanes of a half-warp)
#pragma unroll
        for (int i = 0; i < 8; i++) {
            float mx = fmaxf(fmaxf(S[i][0], S[i][1]), fmaxf(S[i][2], S[i][3]));
            mx = fmaxf(mx, __shfl_xor_sync(0xffffffffu, mx, 1));
            mx = fmaxf(mx, __shfl_xor_sync(0xffffffffu, mx, 2));
            mx = fmaxf(mx, __shfl_xor_sync(0xffffffffu, mx, 4));
            mx = fmaxf(mx, __shfl_xor_sync(0xffffffffu, mx, 8));
            float mnew = fmaxf(mrun[i], mx);
            float scale = __expf(mrun[i] - mnew);
            float ls = 0.f;
#pragma unroll
            for (int j = 0; j < 4; j++) { S[i][j] = __expf(S[i][j] - mnew); ls += S[i][j]; }
            ls += __shfl_xor_sync(0xffffffffu, ls, 1);
            ls += __shfl_xor_sync(0xffffffffu, ls, 2);
            ls += __shfl_xor_sync(0xffffffffu, ls, 4);
            ls += __shfl_xor_sync(0xffffffffu, ls, 8);
            lrun[i] = lrun[i] * scale + ls;
            mrun[i] = mnew;
#pragma unroll
            for (int j = 0; j < 4; j++) O[i][j] *= scale;
        }

        // ---- stage P^T to smem ----
#pragma unroll
        for (int j = 0; j < 4; j++) {
            *(float4*)&psT[(tx * 4 + j) * 132 + ty * 8] =
                make_float4(S[0][j], S[1][j], S[2][j], S[3][j]);
            *(float4*)&psT[(tx * 4 + j) * 132 + ty * 8 + 4] =
                make_float4(S[4][j], S[5][j], S[6][j], S[7][j]);
        }
        __syncthreads();

        // ---- O += P . V^T ----
#pragma unroll 4
        for (int m = 0; m < 64; m++) {
            float4 v4 = *(const float4*)&vsT[m * 68 + tx * 4];
            float4 p0v = *(const float4*)&psT[m * 132 + ty * 8];
            float4 p1v = *(const float4*)&psT[m * 132 + ty * 8 + 4];
            float vv[4] = {v4.x, v4.y, v4.z, v4.w};
            float pv[8] = {p0v.x, p0v.y, p0v.z, p0v.w, p1v.x, p1v.y, p1v.z, p1v.w};
#pragma unroll
            for (int i = 0; i < 8; i++)
#pragma unroll
                for (int j = 0; j < 4; j++) O[i][j] += pv[i] * vv[j];
        }
    }

#pragma unroll
    for (int i = 0; i < 8; i++) {
        float inv = 1.f / lrun[i];
        int n = n0 + ty * 8 + i;
        *(float4*)&g_z[a][b][n * 64 + tx * 4] =
            make_float4(O[i][0] * inv, O[i][1] * inv, O[i][2] * inv, O[i][3] * inv);
    }
}

// ---------------- 3x3 conv: y[o,y,x] = sum_{i,dy,dx} w * comb ---------------
// grid (64 rows, 4 o-tiles, BATCH), block computes 64 o x 64 x for one row.
__global__ __launch_bounds__(256) void conv3x3_kernel(
    const float* __restrict__ cw, const float* __restrict__ cb)
{
    __shared__ float ins[8][3][72];   // [ic][dy][x+1], zero-padded halo
    __shared__ float ws[8][9][64];    // [ic][tap][o]
    const int y = blockIdx.x, ot = blockIdx.y, b = blockIdx.z;
    const int o0 = ot * 64;
    const int tid = threadIdx.x;
    const int tx = tid & 15, ty = tid >> 4;

    float acc[4][4];
#pragma unroll
    for (int a = 0; a < 4; a++)
#pragma unroll
        for (int j = 0; j < 4; j++) acc[a][j] = 0.f;

    for (int ic0 = 0; ic0 < 128; ic0 += 8) {
        __syncthreads();
        for (int idx = tid; idx < 8 * 3 * 66; idx += 256) {
            int ii = idx / 198; int rem = idx - ii * 198;
            int dy = rem / 66;  int xx = rem - dy * 66;
            int yy = y + dy - 1, x = xx - 1;
            float v = 0.f;
            if (yy >= 0 && yy < 64 && x >= 0 && x < 64)
                v = g_comb[b][ic0 + ii][yy * 64 + x];
            ins[ii][dy][xx] = v;
        }
        for (int idx = tid; idx < 8 * 9 * 64; idx += 256) {
            int ii = idx / 576; int rem = idx - ii * 576;
            int tap = rem >> 6; int o = rem & 63;
            ws[ii][tap][o] = cw[((o0 + o) * 128 + ic0 + ii) * 9 + tap];
        }
        __syncthreads();

#pragma unroll
        for (int ii = 0; ii < 8; ii++) {
#pragma unroll
            for (int dy = 0; dy < 3; dy++) {
                float iv[6];
#pragma unroll
                for (int t = 0; t < 6; t++) iv[t] = ins[ii][dy][tx * 4 + t];
#pragma unroll
                for (int dx = 0; dx < 3; dx++) {
                    float4 w4 = *(const float4*)&ws[ii][dy * 3 + dx][ty * 4];
                    float wr[4] = {w4.x, w4.y, w4.z, w4.w};
#pragma unroll
                    for (int a = 0; a < 4; a++)
#pragma unroll
                        for (int j = 0; j < 4; j++)
                            acc[a][j] += wr[a] * iv[j + dx];
                }
            }
        }
    }

#pragma unroll
    for (int a = 0; a < 4; a++) {
        int o = o0 + ty * 4 + a;
        float bb = cb[o];
#pragma unroll
        for (int j = 0; j < 4; j++)
            g_y[b][o][y * 64 + tx * 4 + j] = acc[a][j] + bb;
    }
}

// ---------------- GroupNorm(per-channel) stats ------------------------------
__global__ __launch_bounds__(256) void gnstats_kernel()
{
    __shared__ float s1[256], s2[256];
    const int o = blockIdx.x, b = blockIdx.y;
    const float* yp = &g_y[b][o][0];
    float s = 0.f, ss = 0.f;
    for (int p = threadIdx.x; p < HW; p += 256) {
        float v = yp[p]; s += v; ss += v * v;
    }
    s1[threadIdx.x] = s; s2[threadIdx.x] = ss;
    __syncthreads();
    for (int st = 128; st > 0; st >>= 1) {
        if (threadIdx.x < st) {
            s1[threadIdx.x] += s1[threadIdx.x + st];
            s2[threadIdx.x] += s2[threadIdx.x + st];
        }
        __syncthreads();
    }
    if (threadIdx.x == 0) {
        float mean = s1[0] * (1.f / HW);
        float var  = s2[0] * (1.f / HW) - mean * mean;
        g_mean[b][o] = mean;
        g_rstd[b][o] = rsqrtf(var + 1e-5f);
    }
}

// ---------------- LSTM gates + output ---------------------------------------
__global__ __launch_bounds__(256) void gates_kernel(
    const float* __restrict__ cprev, const float* __restrict__ gnw,
    const float* __restrict__ gnb, float* __restrict__ out)
{
    int idx = blockIdx.x * 256 + threadIdx.x;   // over BATCH*64*HW
    if (idx >= BATCH * 64 * HW) return;
    int p  = idx & (HW - 1);
    int ch = (idx >> 12) & 63;
    int b  = idx >> 18;

    float ni, nf, no_, ng;
    {
        int o = ch;
        ni = (g_y[b][o][p] - g_mean[b][o]) * g_rstd[b][o] * gnw[o] + gnb[o];
        o = ch + 64;
        nf = (g_y[b][o][p] - g_mean[b][o]) * g_rstd[b][o] * gnw[o] + gnb[o];
        o = ch + 128;
        no_ = (g_y[b][o][p] - g_mean[b][o]) * g_rstd[b][o] * gnw[o] + gnb[o];
        o = ch + 192;
        ng = (g_y[b][o][p] - g_mean[b][o]) * g_rstd[b][o] * gnw[o] + gnb[o];
    }
    float ig = 1.f / (1.f + __expf(-ni));
    float fg = 1.f / (1.f + __expf(-nf));
    float og = 1.f / (1.f + __expf(-no_));
    float gg = tanhf(ng);
    float cn = fg * cprev[idx] + ig * gg;
    float hn = og * tanhf(cn);
    out[idx] = hn;                       // h_next
    out[idx + BATCH * 64 * HW] = cn;     // c_next
}

// ---------------- launch -----------------------------------------------------
extern "C" void kernel_launch(void* const* d_in, const int* in_sizes, int n_in,
                              void* d_out, int out_size)
{
    (void)in_sizes; (void)n_in; (void)out_size;
    const float* x = (const float*)d_in[0];
    const float* h = (const float*)d_in[1];
    const float* c = (const float*)d_in[2];
    const float* aw[2][8];
    for (int a = 0; a < 2; a++)
        for (int j = 0; j < 8; j++)
            aw[a][j] = (const float*)d_in[3 + a * 8 + j];
    const float* conv_w = (const float*)d_in[19];
    const float* conv_b = (const float*)d_in[20];
    const float* gn_w   = (const float*)d_in[21];
    const float* gn_b   = (const float*)d_in[22];
    float* out = (float*)d_out;

    float *q, *k, *v, *z, *comb;
    cudaGetSymbolAddress((void**)&q, g_q);
    cudaGetSymbolAddress((void**)&k, g_k);
    cudaGetSymbolAddress((void**)&v, g_v);
    cudaGetSymbolAddress((void**)&z, g_z);
    cudaGetSymbolAddress((void**)&comb, g_comb);

    cudaFuncSetAttribute(gemm1x1_kernel,
                         cudaFuncAttributeMaxDynamicSharedMemorySize, 49152);
    cudaFuncSetAttribute(flash_kernel,
                         cudaFuncAttributeMaxDynamicSharedMemorySize,
                         FLASH_SMEM_FLOATS * 4);

    const dim3 g32(32, BATCH);
    const size_t gsm = 49152;
    const float* src[2] = {x, h};

    // q,k,v projections for both attention blocks
    for (int a = 0; a < 2; a++) {
        gemm1x1_kernel<<<g32, 256, gsm>>>(src[a], aw[a][0], aw[a][1],
                                          nullptr, nullptr,
                                          q + (size_t)a * BATCH * 64 * HW, 64 * HW);
        gemm1x1_kernel<<<g32, 256, gsm>>>(src[a], aw[a][2], aw[a][3],
                                          nullptr, nullptr,
                                          k + (size_t)a * BATCH * 64 * HW, 64 * HW);
        gemm1x1_kernel<<<g32, 256, gsm>>>(src[a], aw[a][4], aw[a][5],
                                          nullptr, nullptr,
                                          v + (size_t)a * BATCH * 64 * HW, 64 * HW);
    }

    // flash attention (both blocks, all batches)
    flash_kernel<<<dim3(32, BATCH, 2), 256, FLASH_SMEM_FLOATS * 4>>>();

    // f-projection with fused (z-reshape * input) and residual, into concat buf
    for (int a = 0; a < 2; a++)
        gemm1x1_kernel<<<g32, 256, gsm>>>(src[a], aw[a][6], aw[a][7],
                                          z + (size_t)a * BATCH * HW * 64, src[a],
                                          comb + (size_t)a * 64 * HW, 128 * HW);

    conv3x3_kernel<<<dim3(64, 4, BATCH), 256>>>(conv_w, conv_b);
    gnstats_kernel<<<dim3(256, BATCH), 256>>>();
    gates_kernel<<<(BATCH * 64 * HW) / 256, 256>>>(c, gn_w, gn_b, out);
}